// round 9
// baseline (speedup 1.0000x reference)
#include <cuda_runtime.h>
#include <cuda_bf16.h>
#include <cstdint>
#include <math.h>

#define BB   16
#define LLEN 1024
#define HH   256
#define NN2  64
#define NBK  6
#define TT   (BB*LLEN)

typedef unsigned long long u64;

// ---------------- scratch (device globals; no allocation allowed) ----------------
__device__ float g_zbuf[(TT+32)*HH];
#define G_Z (g_zbuf + 16*HH)
__device__ float g_x[TT*HH];
__device__ float g_yf[TT*HH];
__device__ float g_yb[TT*HH];
__device__ float g_g[TT*HH];
__device__ float g_skip[TT*HH];
__device__ float g_h[TT*HH];
__device__ float g_tb[NBK*BB*HH];
__device__ float g_wre[NBK*HH*NN2], g_wim[NBK*HH*NN2];
__device__ float g_b0re[NBK*HH*NN2], g_b0im[NBK*HH*NN2];
__device__ float g_b1re[NBK*HH*NN2], g_b1im[NBK*HH*NN2];

// ---------------- packed fp32x2 helpers (sm_103a) ----------------
__device__ __forceinline__ u64 f2fma(u64 a, u64 b, u64 c){
  u64 d; asm("fma.rn.f32x2 %0, %1, %2, %3;" : "=l"(d) : "l"(a), "l"(b), "l"(c)); return d;
}
__device__ __forceinline__ u64 f2mul(u64 a, u64 b){
  u64 d; asm("mul.rn.f32x2 %0, %1, %2;" : "=l"(d) : "l"(a), "l"(b)); return d;
}
__device__ __forceinline__ u64 f2pack(float lo, float hi){
  u64 d; asm("mov.b64 %0, {%1, %2};" : "=l"(d) : "f"(lo), "f"(hi)); return d;
}
__device__ __forceinline__ float2 f2unpack(u64 v){
  float2 r; asm("mov.b64 {%0, %1}, %2;" : "=f"(r.x), "=f"(r.y) : "l"(v)); return r;
}

// ---------------- launch 1: ALL setup in one kernel ----------------
__global__ void k_setup(const float* __restrict__ log_dt, const float* __restrict__ A_re,
                        const float* __restrict__ A_im, const float* __restrict__ C_re,
                        const float* __restrict__ C_im,
                        const float* __restrict__ tt, const float* __restrict__ W1,
                        const float* __restrict__ b1v, const float* __restrict__ W2,
                        const float* __restrict__ b2v,
                        const float* __restrict__ Wt, const float* __restrict__ bt,
                        const float* __restrict__ input, const float* __restrict__ W_in,
                        const float* __restrict__ b_in){
  __shared__ float s1[128];
  __shared__ float s2[256];
  __shared__ float te[256];
  if (blockIdx.x < 384){
    int idx = blockIdx.x*256 + threadIdx.x;
    int i   = idx / (HH*NN2);
    int rem = idx % (HH*NN2);
    int h   = rem / NN2;
    int n   = rem % NN2;
    float dt  = expf(log_dt[i*HH + h]);
    float are = A_re[idx], aim = A_im[idx];
    float dre = -dt*are, dim = dt*aim;
    float er  = expf(dre);
    float wre = er*cosf(dim), wim = er*sinf(dim);
    g_wre[idx] = wre; g_wim[idx] = wim;
    float dinv = 1.f/(are*are + aim*aim);
    float ure = wre - 1.f, uim = wim;
    float qre = (-ure*are + uim*aim)*dinv;
    float qim = (-uim*are - ure*aim)*dinv;
    size_t c0 = (((size_t)i*2 + 0)*HH + h)*NN2 + n;
    size_t c1 = (((size_t)i*2 + 1)*HH + h)*NN2 + n;
    float cr = C_re[c0], ci = C_im[c0];
    g_b0re[idx] = cr*qre - ci*qim;
    g_b0im[idx] = cr*qim + ci*qre;
    cr = C_re[c1]; ci = C_im[c1];
    g_b1re[idx] = cr*qre - ci*qim;
    g_b1im[idx] = cr*qim + ci*qre;
  } else if (blockIdx.x < 480){
    int blk = blockIdx.x - 384;
    int b = blk & 15;
    int i = blk >> 4;
    int h = threadIdx.x;
    if (h < 128){
      int j = h & 63;
      float fr = expf(-(float)j * (9.210340371976184f/63.f));
      float ang = tt[b]*fr;
      s1[h] = (h < 64) ? sinf(ang) : cosf(ang);
    }
    __syncthreads();
    float acc = b1v[h];
    #pragma unroll 4
    for (int k=0;k<128;k++) acc = fmaf(s1[k], W1[k*HH+h], acc);
    acc = acc / (1.f + expf(-acc));
    s2[h] = acc;
    __syncthreads();
    float a2 = b2v[h];
    #pragma unroll 4
    for (int k=0;k<HH;k++) a2 = fmaf(s2[k], W2[k*HH+h], a2);
    a2 = a2 / (1.f + expf(-a2));
    te[h] = a2;
    __syncthreads();
    float tbv = bt[i*HH + h];
    const float* wp = Wt + (size_t)i*HH*HH + h;
    #pragma unroll 4
    for (int k=0;k<HH;k++) tbv = fmaf(te[k], wp[(size_t)k*HH], tbv);
    g_tb[blk*HH + h] = tbv;
  } else {
    int idx = (blockIdx.x-480)*256 + threadIdx.x;
    int t = idx >> 8; int h = idx & 255;
    g_x[idx] = fmaxf(fmaf(input[t], W_in[h], b_in[h]), 0.f);
    g_skip[idx] = 0.f;
  }
}

// ---------------- u = x + tb; LayerNorm over H -> G_Z ----------------
__global__ void __launch_bounds__(256) k_ln(int i, const float* __restrict__ lg,
                                            const float* __restrict__ lb){
  int warp = threadIdx.x >> 5, lane = threadIdx.x & 31;
  int t = blockIdx.x*8 + warp;
  int b = t >> 10;
  const float* xr = g_x  + (size_t)t*HH + lane*8;
  const float* tr = g_tb + ((size_t)i*BB + b)*HH + lane*8;
  float4 v0 = *(const float4*)xr;      float4 v1 = *(const float4*)(xr+4);
  float4 t0 = *(const float4*)tr;      float4 t1 = *(const float4*)(tr+4);
  float u[8];
  u[0]=v0.x+t0.x; u[1]=v0.y+t0.y; u[2]=v0.z+t0.z; u[3]=v0.w+t0.w;
  u[4]=v1.x+t1.x; u[5]=v1.y+t1.y; u[6]=v1.z+t1.z; u[7]=v1.w+t1.w;
  float s=0.f, q=0.f;
  #pragma unroll
  for (int j=0;j<8;j++){ s += u[j]; q += u[j]*u[j]; }
  #pragma unroll
  for (int o=16;o>0;o>>=1){
    s += __shfl_xor_sync(0xffffffffu, s, o);
    q += __shfl_xor_sync(0xffffffffu, q, o);
  }
  float mu = s * (1.f/HH);
  float var = q*(1.f/HH) - mu*mu;
  float rs = rsqrtf(var + 1e-5f);
  const float* gp = lg + i*HH + lane*8;
  const float* bp = lb + i*HH + lane*8;
  float4 g0=*(const float4*)gp, g1=*(const float4*)(gp+4);
  float4 e0=*(const float4*)bp, e1=*(const float4*)(bp+4);
  float4 z0, z1;
  z0.x=(u[0]-mu)*rs*g0.x+e0.x; z0.y=(u[1]-mu)*rs*g0.y+e0.y;
  z0.z=(u[2]-mu)*rs*g0.z+e0.z; z0.w=(u[3]-mu)*rs*g0.w+e0.w;
  z1.x=(u[4]-mu)*rs*g1.x+e1.x; z1.y=(u[5]-mu)*rs*g1.y+e1.y;
  z1.z=(u[6]-mu)*rs*g1.z+e1.z; z1.w=(u[7]-mu)*rs*g1.w+e1.w;
  float* zp = G_Z + (size_t)t*HH + lane*8;
  *(float4*)zp = z0; *(float4*)(zp+4) = z1;
}

// ---------------- scan step helpers (4 f32x2 pairs = 8 complex states/thread) ----------------
__device__ __forceinline__ float scan_step_fwd(float zv, u64* sre, u64* sim,
    const u64* wre, const u64* wim, const u64* nwim, const u64* btr, const u64* nbti){
  u64 zz = f2pack(zv, zv);
  u64 acc = 0ULL;
  #pragma unroll
  for (int p=0;p<4;p++){
    u64 t0 = f2fma(nwim[p], sim[p], zz);
    u64 ns = f2fma(wre[p], sim[p], f2mul(wim[p], sre[p]));
    sre[p] = f2fma(wre[p], sre[p], t0);
    sim[p] = ns;
    acc = f2fma(btr[p], sre[p], f2fma(nbti[p], sim[p], acc));
  }
  float2 a = f2unpack(acc);
  return a.x + a.y;
}
__device__ __forceinline__ float scan_step_bwd(float zv, u64* sre, u64* sim,
    const u64* wre, const u64* wim, const u64* nwim, const u64* btr, const u64* nbti){
  u64 acc = 0ULL;
  #pragma unroll
  for (int p=0;p<4;p++)
    acc = f2fma(btr[p], sre[p], f2fma(nbti[p], sim[p], acc));
  u64 zz = f2pack(zv, zv);
  #pragma unroll
  for (int p=0;p<4;p++){
    u64 t0 = f2fma(nwim[p], sim[p], zz);
    u64 ns = f2fma(wre[p], sim[p], f2mul(wim[p], sre[p]));
    sre[p] = f2fma(wre[p], sre[p], t0);
    sim[p] = ns;
  }
  float2 a = f2unpack(acc);
  return a.x + a.y;
}

// ---------------- bidirectional diagonal-SSM scan (R5 config) ----------------
__global__ void __launch_bounds__(128) k_scan(int i){
  int tid = threadIdx.x;
  int bid = blockIdx.x;
  int dir = bid & 1;
  int q   = bid >> 1;
  int htile = q & 15;
  int b = q >> 4;
  int hl = tid >> 3, sg = tid & 7;
  int h = htile*16 + hl;
  bool bit2 = (sg & 4) != 0, bit1 = (sg & 2) != 0, bit0 = (sg & 1) != 0;
  size_t pb = ((size_t)i*HH + h)*NN2 + sg*8;
  const u64* wre_p = (const u64*)(g_wre + pb);
  const u64* wim_p = (const u64*)(g_wim + pb);
  const u64* bre_p = (const u64*)((dir ? g_b1re : g_b0re) + pb);
  const u64* bim_p = (const u64*)((dir ? g_b1im : g_b0im) + pb);
  const u64 SGN = 0x8000000080000000ULL;
  u64 wre[4], wim[4], nwim[4], btr[4], nbti[4];
  #pragma unroll
  for (int p=0;p<4;p++){
    wre[p]=wre_p[p]; wim[p]=wim_p[p]; nwim[p]=wim[p]^SGN;
    btr[p]=bre_p[p]; nbti[p]=bim_p[p]^SGN;
  }
  u64 sre[4]={0,0,0,0}, sim[4]={0,0,0,0};
  int start = dir ? (LLEN-1) : 0;
  const int st = dir ? -HH : HH;
  const float* zc = G_Z + ((size_t)b*LLEN + start)*HH + h;
  float* yc = (dir ? g_yb : g_yf) + ((size_t)b*LLEN + start)*HH + h;

  float zs[8];
  #pragma unroll
  for (int j=0;j<8;j++) zs[j] = zc[j*st];

  #pragma unroll 1
  for (int l0=0;l0<LLEN;l0+=8){
    float zn[8];
    #pragma unroll
    for (int j=0;j<8;j++) zn[j] = zc[(8+j)*st];
    float p[8];
    if (dir == 0){
      #pragma unroll
      for (int j=0;j<8;j++) p[j] = scan_step_fwd(zs[j], sre, sim, wre, wim, nwim, btr, nbti);
    } else {
      #pragma unroll
      for (int j=0;j<8;j++) p[j] = scan_step_bwd(zs[j], sre, sim, wre, wim, nwim, btr, nbti);
    }
    float q1[4];
    #pragma unroll
    for (int j=0;j<4;j++){
      float snd = bit2 ? p[j] : p[j+4];
      float r = __shfl_xor_sync(0xffffffffu, snd, 4);
      q1[j] = (bit2 ? p[j+4] : p[j]) + r;
    }
    float s0 = bit1 ? q1[0] : q1[2];
    float s1v = bit1 ? q1[1] : q1[3];
    float r0 = __shfl_xor_sync(0xffffffffu, s0, 2);
    float r1 = __shfl_xor_sync(0xffffffffu, s1v, 2);
    float u0 = (bit1 ? q1[2] : q1[0]) + r0;
    float u1 = (bit1 ? q1[3] : q1[1]) + r1;
    float s2v = bit0 ? u0 : u1;
    float r2 = __shfl_xor_sync(0xffffffffu, s2v, 1);
    float y  = (bit0 ? u1 : u0) + r2;
    yc[sg*st] = 2.f*y;
    #pragma unroll
    for (int j=0;j<8;j++) zs[j] = zn[j];
    zc += 8*st; yc += 8*st;
  }
}

// ---------------- fp32x2 SIMT GEMM v3: pipelined staging ----------------
// BM=128, BN=128, BK=32, 128 threads; per-thread 16M x 8N (M-pairs in f32x2).
// Global loads for tile k0+1 are issued BEFORE the k0 mainloop (held in regs),
// so stores at the next staging point complete without exposing latency.
template<int EPI>
__global__ void __launch_bounds__(128, 2) k_gemm(const float* __restrict__ W,
        const float* __restrict__ bias, const float* __restrict__ feat,
        const float* __restrict__ Wf, const float* __restrict__ bf, int iblk,
        const float* __restrict__ Dp){
  __shared__ float As[32*128];   // [k][m]
  __shared__ float Bs[32*128];   // [k][n]
  __shared__ float Ds[256];
  int tid = threadIdx.x;
  int m0 = blockIdx.x * 128;
  int n0 = blockIdx.y * 128;
  int mi = tid >> 4;    // 0..7 -> rows mi*16..+16
  int ni = tid & 15;    // 0..15 -> cols ni*8..+8
  u64 acc[8][8];
  #pragma unroll
  for (int mp=0;mp<8;mp++)
    #pragma unroll
    for (int n=0;n<8;n++) acc[mp][n] = 0ULL;

  const float* Ap = nullptr;
  const float* Af = nullptr; const float* Ab = nullptr; const float* Az = nullptr;
  if (EPI==0){
    Af = g_yf + (size_t)(m0 + tid)*HH;
    Ab = g_yb + (size_t)(m0 + tid)*HH;
    Az = G_Z  + (size_t)(m0 + tid)*HH;
    Ds[tid] = Dp[tid]; Ds[tid+128] = Dp[tid+128];
  } else {
    const float* A = (EPI==3) ? g_skip : g_g;
    Ap = A + (size_t)(m0 + tid)*HH;
  }

  // prefetch tile k0=0 into regs (B always; A only for EPI!=0)
  float4 pa[8]; float4 pb[8];
  if (EPI!=0){
    #pragma unroll
    for (int c=0;c<8;c++) pa[c] = *(const float4*)(Ap + c*4);
  }
  #pragma unroll
  for (int it=0;it<8;it++){
    int f = tid + it*128;
    int kk = f >> 5;
    int cc = (f & 31) * 4;
    pb[it] = *(const float4*)(W + (size_t)kk*HH + n0 + cc);
  }

  for (int k0=0;k0<HH;k0+=32){
    __syncthreads();    // smem free (prev mainloop done); also orders Ds init
    // ---- store A tile ----
    if (EPI==0){
      // chunked direct load+gelu (MLP 12 per chunk)
      #pragma unroll
      for (int cc4=0;cc4<2;cc4++){
        float4 vf[4], vb[4], vz[4];
        #pragma unroll
        for (int c=0;c<4;c++){
          int cg = cc4*4 + c;
          vf[c] = *(const float4*)(Af + k0 + cg*4);
          vb[c] = *(const float4*)(Ab + k0 + cg*4);
          vz[c] = *(const float4*)(Az + k0 + cg*4);
        }
        #pragma unroll
        for (int c=0;c<4;c++){
          int cg = cc4*4 + c;
          float4 d4 = *(const float4*)(Ds + k0 + cg*4);
          float w0 = vf[c].x + vb[c].x + vz[c].x*d4.x;
          float w1 = vf[c].y + vb[c].y + vz[c].y*d4.y;
          float w2 = vf[c].z + vb[c].z + vz[c].z*d4.z;
          float w3 = vf[c].w + vb[c].w + vz[c].w*d4.w;
          As[(cg*4+0)*128 + tid] = 0.5f*w0*(1.f + erff(w0*0.70710678118f));
          As[(cg*4+1)*128 + tid] = 0.5f*w1*(1.f + erff(w1*0.70710678118f));
          As[(cg*4+2)*128 + tid] = 0.5f*w2*(1.f + erff(w2*0.70710678118f));
          As[(cg*4+3)*128 + tid] = 0.5f*w3*(1.f + erff(w3*0.70710678118f));
        }
      }
    } else {
      #pragma unroll
      for (int c=0;c<8;c++){
        As[(c*4+0)*128 + tid] = pa[c].x;
        As[(c*4+1)*128 + tid] = pa[c].y;
        As[(c*4+2)*128 + tid] = pa[c].z;
        As[(c*4+3)*128 + tid] = pa[c].w;
      }
    }
    // ---- store B tile ----
    #pragma unroll
    for (int it=0;it<8;it++){
      int f = tid + it*128;
      int kk = f >> 5;
      int cc = (f & 31) * 4;
      *(float4*)(Bs + kk*128 + cc) = pb[it];
    }
    // ---- issue prefetch for k0+1 (lands during mainloop) ----
    if (k0 + 32 < HH){
      if (EPI!=0){
        #pragma unroll
        for (int c=0;c<8;c++) pa[c] = *(const float4*)(Ap + k0 + 32 + c*4);
      }
      #pragma unroll
      for (int it=0;it<8;it++){
        int f = tid + it*128;
        int kk = f >> 5;
        int cc = (f & 31) * 4;
        pb[it] = *(const float4*)(W + (size_t)(k0+32+kk)*HH + n0 + cc);
      }
    }
    __syncthreads();
    // ---- mainloop ----
    #pragma unroll 4
    for (int k=0;k<32;k++){
      const ulonglong2* ap = (const ulonglong2*)(As + k*128 + mi*16);
      ulonglong2 qa0 = ap[0], qa1 = ap[1], qa2 = ap[2], qa3 = ap[3];
      u64 am[8] = {qa0.x,qa0.y,qa1.x,qa1.y,qa2.x,qa2.y,qa3.x,qa3.y};
      float4 b0 = *(const float4*)(Bs + k*128 + ni*8);
      float4 b1 = *(const float4*)(Bs + k*128 + ni*8 + 4);
      u64 bn[8] = {f2pack(b0.x,b0.x), f2pack(b0.y,b0.y), f2pack(b0.z,b0.z), f2pack(b0.w,b0.w),
                   f2pack(b1.x,b1.x), f2pack(b1.y,b1.y), f2pack(b1.z,b1.z), f2pack(b1.w,b1.w)};
      #pragma unroll
      for (int mp=0;mp<8;mp++)
        #pragma unroll
        for (int n=0;n<8;n++)
          acc[mp][n] = f2fma(am[mp], bn[n], acc[mp][n]);
    }
  }

  int mbase = m0 + mi*16;
  int nbase = n0 + ni*8;
  float bsv[8];
  #pragma unroll
  for (int n=0;n<8;n++) bsv[n] = bias[nbase+n];
  float wf0[8], wf1[8], wf2[8], wf3[8], bfv[8];
  const float* tbp = nullptr;
  if (EPI==0){
    #pragma unroll
    for (int c=0;c<2;c++){
      float4 a0 = *(const float4*)(Wf + 0*HH + nbase + c*4);
      float4 a1 = *(const float4*)(Wf + 1*HH + nbase + c*4);
      float4 a2 = *(const float4*)(Wf + 2*HH + nbase + c*4);
      float4 a3 = *(const float4*)(Wf + 3*HH + nbase + c*4);
      wf0[c*4+0]=a0.x; wf0[c*4+1]=a0.y; wf0[c*4+2]=a0.z; wf0[c*4+3]=a0.w;
      wf1[c*4+0]=a1.x; wf1[c*4+1]=a1.y; wf1[c*4+2]=a1.z; wf1[c*4+3]=a1.w;
      wf2[c*4+0]=a2.x; wf2[c*4+1]=a2.y; wf2[c*4+2]=a2.z; wf2[c*4+3]=a2.w;
      wf3[c*4+0]=a3.x; wf3[c*4+1]=a3.y; wf3[c*4+2]=a3.z; wf3[c*4+3]=a3.w;
    }
    #pragma unroll
    for (int c=0;c<2;c++){
      float4 bv = *(const float4*)(bf + nbase + c*4);
      bfv[c*4+0]=bv.x; bfv[c*4+1]=bv.y; bfv[c*4+2]=bv.z; bfv[c*4+3]=bv.w;
    }
    tbp = g_tb + ((size_t)iblk*BB + (mbase>>10))*HH;
  }

  #pragma unroll
  for (int mp=0;mp<8;mp++){
    #pragma unroll
    for (int e=0;e<2;e++){
      size_t t = (size_t)mbase + mp*2 + e;
      float c[8];
      #pragma unroll
      for (int n=0;n<8;n++){
        float2 v = f2unpack(acc[mp][n]);
        c[n] = (e ? v.y : v.x) + bsv[n];
      }
      if (EPI==0){
        float4 fq = *(const float4*)(feat + t*4);
        const float* xp = g_x + t*HH + nbase;
        float4 x0 = *(const float4*)xp, x1 = *(const float4*)(xp+4);
        float xv[8] = {x0.x,x0.y,x0.z,x0.w,x1.x,x1.y,x1.z,x1.w};
        float o[8];
        #pragma unroll
        for (int n=0;n<8;n++){
          float r = c[n] + xv[n] + tbp[nbase+n] + bfv[n]
                  + fq.x*wf0[n] + fq.y*wf1[n] + fq.z*wf2[n] + fq.w*wf3[n];
          o[n] = tanhf(r) * (1.f/(1.f+expf(-r)));
        }
        float* gp = g_g + t*HH + nbase;
        *(float4*)gp     = make_float4(o[0],o[1],o[2],o[3]);
        *(float4*)(gp+4) = make_float4(o[4],o[5],o[6],o[7]);
      } else if (EPI==1){
        float* xp = g_x + t*HH + nbase;
        float4 x0 = *(const float4*)xp, x1 = *(const float4*)(xp+4);
        *(float4*)xp     = make_float4(x0.x+c[0], x0.y+c[1], x0.z+c[2], x0.w+c[3]);
        *(float4*)(xp+4) = make_float4(x1.x+c[4], x1.y+c[5], x1.z+c[6], x1.w+c[7]);
      } else if (EPI==2){
        float* sp = g_skip + t*HH + nbase;
        float4 s0 = *(const float4*)sp, s1 = *(const float4*)(sp+4);
        *(float4*)sp     = make_float4(s0.x+c[0], s0.y+c[1], s0.z+c[2], s0.w+c[3]);
        *(float4*)(sp+4) = make_float4(s1.x+c[4], s1.y+c[5], s1.z+c[6], s1.w+c[7]);
      } else {
        float* hp = g_h + t*HH + nbase;
        *(float4*)hp     = make_float4(fmaxf(c[0],0.f), fmaxf(c[1],0.f), fmaxf(c[2],0.f), fmaxf(c[3],0.f));
        *(float4*)(hp+4) = make_float4(fmaxf(c[4],0.f), fmaxf(c[5],0.f), fmaxf(c[6],0.f), fmaxf(c[7],0.f));
      }
    }
  }
}

// out[t] = h[t,:] . Wh2 + bh2 + input[t]
__global__ void __launch_bounds__(256) k_final(const float* __restrict__ Wh2,
        const float* __restrict__ bh2, const float* __restrict__ input,
        float* __restrict__ out){
  int warp = threadIdx.x >> 5, lane = threadIdx.x & 31;
  int t = blockIdx.x*8 + warp;
  const float* hp = g_h + (size_t)t*HH + lane*8;
  const float* wp = Wh2 + lane*8;
  float4 h0=*(const float4*)hp, h1=*(const float4*)(hp+4);
  float4 w0=*(const float4*)wp, w1=*(const float4*)(wp+4);
  float s = h0.x*w0.x + h0.y*w0.y + h0.z*w0.z + h0.w*w0.w
          + h1.x*w1.x + h1.y*w1.y + h1.z*w1.z + h1.w*w1.w;
  #pragma unroll
  for (int o=16;o>0;o>>=1) s += __shfl_xor_sync(0xffffffffu, s, o);
  if (lane == 0) out[t] = s + bh2[0] + input[t];
}

extern "C" void kernel_launch(void* const* d_in, const int* in_sizes, int n_in,
                              void* d_out, int out_size){
  (void)in_sizes; (void)n_in; (void)out_size;
  const float* input = (const float*)d_in[0];
  const float* tvec  = (const float*)d_in[1];
  const float* feat  = (const float*)d_in[2];
  const float* W_in  = (const float*)d_in[3];
  const float* b_in  = (const float*)d_in[4];
  const float* W_t1  = (const float*)d_in[5];
  const float* b_t1  = (const float*)d_in[6];
  const float* W_t2  = (const float*)d_in[7];
  const float* b_t2  = (const float*)d_in[8];
  const float* Wh1   = (const float*)d_in[9];
  const float* bh1   = (const float*)d_in[10];
  const float* Wh2   = (const float*)d_in[11];
  const float* bh2   = (const float*)d_in[12];
  const float* ln_g  = (const float*)d_in[13];
  const float* ln_b  = (const float*)d_in[14];
  const float* log_dt= (const float*)d_in[15];
  const float* A_re  = (const float*)d_in[16];
  const float* A_im  = (const float*)d_in[17];
  const float* C_re  = (const float*)d_in[18];
  const float* C_im  = (const float*)d_in[19];
  const float* Dd    = (const float*)d_in[20];
  const float* Wo_s4 = (const float*)d_in[21];
  const float* bo_s4 = (const float*)d_in[22];
  const float* Wt    = (const float*)d_in[23];
  const float* bt    = (const float*)d_in[24];
  const float* W1    = (const float*)d_in[25];
  const float* b1    = (const float*)d_in[26];
  const float* W2    = (const float*)d_in[27];
  const float* b2    = (const float*)d_in[28];
  const float* Wf    = (const float*)d_in[29];
  const float* bf    = (const float*)d_in[30];
  float* out = (float*)d_out;

  // launch #1: all setup
  k_setup<<<480 + TT*HH/256, 256>>>(log_dt, A_re, A_im, C_re, C_im,
                                    tvec, W_t1, b_t1, W_t2, b_t2,
                                    Wt, bt, input, W_in, b_in);

  dim3 gg(TT/128, HH/128);   // 256 blocks, all co-resident at 2 blocks/SM
  for (int i=0;i<NBK;i++){
    k_ln<<<TT/8, 256>>>(i, ln_g, ln_b);        // launch #2 (i=0)
    k_scan<<<512, 128>>>(i);                   // launch #3 (i=0)
    k_gemm<0><<<gg, 128>>>(Wo_s4 + (size_t)i*HH*HH, bo_s4 + i*HH,
                           feat, Wf + (size_t)i*4*HH, bf + i*HH, i,
                           Dd + i*HH);         // launch #4 (i=0) -> profiled slot
    k_gemm<1><<<gg, 128>>>(W1 + (size_t)i*HH*HH, b1 + i*HH, nullptr, nullptr, nullptr, i, nullptr);
    k_gemm<2><<<gg, 128>>>(W2 + (size_t)i*HH*HH, b2 + i*HH, nullptr, nullptr, nullptr, i, nullptr);
  }
  k_gemm<3><<<gg, 128>>>(Wh1, bh1, nullptr, nullptr, nullptr, 0, nullptr);
  k_final<<<TT/8, 256>>>(Wh2, bh2, input, out);
}

// round 14
// speedup vs baseline: 1.5816x; 1.5816x over previous
#include <cuda_runtime.h>
#include <cuda_bf16.h>
#include <cstdint>
#include <math.h>

#define BB   16
#define LLEN 1024
#define HH   256
#define NN2  64
#define NBK  6
#define TT   (BB*LLEN)

typedef unsigned long long u64;

// ---------------- scratch (device globals; no allocation allowed) ----------------
__device__ float g_zbuf[(TT+32)*HH];
#define G_Z (g_zbuf + 16*HH)
__device__ float g_x[TT*HH];
__device__ float g_yf[TT*HH];
__device__ float g_yb[TT*HH];
__device__ float g_g[TT*HH];
__device__ float g_skip[TT*HH];
__device__ float g_h[TT*HH];
__device__ float g_tb[NBK*BB*HH];
__device__ float g_wre[NBK*HH*NN2], g_wim[NBK*HH*NN2];
__device__ float g_b0re[NBK*HH*NN2], g_b0im[NBK*HH*NN2];
__device__ float g_b1re[NBK*HH*NN2], g_b1im[NBK*HH*NN2];

// ---------------- packed fp32x2 helpers (sm_103a) ----------------
__device__ __forceinline__ u64 f2fma(u64 a, u64 b, u64 c){
  u64 d; asm("fma.rn.f32x2 %0, %1, %2, %3;" : "=l"(d) : "l"(a), "l"(b), "l"(c)); return d;
}
__device__ __forceinline__ u64 f2mul(u64 a, u64 b){
  u64 d; asm("mul.rn.f32x2 %0, %1, %2;" : "=l"(d) : "l"(a), "l"(b)); return d;
}
__device__ __forceinline__ u64 f2pack(float lo, float hi){
  u64 d; asm("mov.b64 %0, {%1, %2};" : "=l"(d) : "f"(lo), "f"(hi)); return d;
}
__device__ __forceinline__ float2 f2unpack(u64 v){
  float2 r; asm("mov.b64 {%0, %1}, %2;" : "=f"(r.x), "=f"(r.y) : "l"(v)); return r;
}

// ---------------- launch 1: ALL setup in one kernel ----------------
__global__ void k_setup(const float* __restrict__ log_dt, const float* __restrict__ A_re,
                        const float* __restrict__ A_im, const float* __restrict__ C_re,
                        const float* __restrict__ C_im,
                        const float* __restrict__ tt, const float* __restrict__ W1,
                        const float* __restrict__ b1v, const float* __restrict__ W2,
                        const float* __restrict__ b2v,
                        const float* __restrict__ Wt, const float* __restrict__ bt,
                        const float* __restrict__ input, const float* __restrict__ W_in,
                        const float* __restrict__ b_in){
  __shared__ float s1[128];
  __shared__ float s2[256];
  __shared__ float te[256];
  if (blockIdx.x < 384){
    int idx = blockIdx.x*256 + threadIdx.x;
    int i   = idx / (HH*NN2);
    int rem = idx % (HH*NN2);
    int h   = rem / NN2;
    int n   = rem % NN2;
    float dt  = expf(log_dt[i*HH + h]);
    float are = A_re[idx], aim = A_im[idx];
    float dre = -dt*are, dim = dt*aim;
    float er  = expf(dre);
    float wre = er*cosf(dim), wim = er*sinf(dim);
    g_wre[idx] = wre; g_wim[idx] = wim;
    float dinv = 1.f/(are*are + aim*aim);
    float ure = wre - 1.f, uim = wim;
    float qre = (-ure*are + uim*aim)*dinv;
    float qim = (-uim*are - ure*aim)*dinv;
    size_t c0 = (((size_t)i*2 + 0)*HH + h)*NN2 + n;
    size_t c1 = (((size_t)i*2 + 1)*HH + h)*NN2 + n;
    float cr = C_re[c0], ci = C_im[c0];
    g_b0re[idx] = cr*qre - ci*qim;
    g_b0im[idx] = cr*qim + ci*qre;
    cr = C_re[c1]; ci = C_im[c1];
    g_b1re[idx] = cr*qre - ci*qim;
    g_b1im[idx] = cr*qim + ci*qre;
  } else if (blockIdx.x < 480){
    int blk = blockIdx.x - 384;
    int b = blk & 15;
    int i = blk >> 4;
    int h = threadIdx.x;
    if (h < 128){
      int j = h & 63;
      float fr = expf(-(float)j * (9.210340371976184f/63.f));
      float ang = tt[b]*fr;
      s1[h] = (h < 64) ? sinf(ang) : cosf(ang);
    }
    __syncthreads();
    float acc = b1v[h];
    #pragma unroll 4
    for (int k=0;k<128;k++) acc = fmaf(s1[k], W1[k*HH+h], acc);
    acc = acc / (1.f + expf(-acc));
    s2[h] = acc;
    __syncthreads();
    float a2 = b2v[h];
    #pragma unroll 4
    for (int k=0;k<HH;k++) a2 = fmaf(s2[k], W2[k*HH+h], a2);
    a2 = a2 / (1.f + expf(-a2));
    te[h] = a2;
    __syncthreads();
    float tbv = bt[i*HH + h];
    const float* wp = Wt + (size_t)i*HH*HH + h;
    #pragma unroll 4
    for (int k=0;k<HH;k++) tbv = fmaf(te[k], wp[(size_t)k*HH], tbv);
    g_tb[blk*HH + h] = tbv;
  } else {
    int idx = (blockIdx.x-480)*256 + threadIdx.x;
    int t = idx >> 8; int h = idx & 255;
    g_x[idx] = fmaxf(fmaf(input[t], W_in[h], b_in[h]), 0.f);
    g_skip[idx] = 0.f;
  }
}

// ---------------- u = x + tb; LayerNorm over H -> G_Z ----------------
__global__ void __launch_bounds__(256) k_ln(int i, const float* __restrict__ lg,
                                            const float* __restrict__ lb){
  int warp = threadIdx.x >> 5, lane = threadIdx.x & 31;
  int t = blockIdx.x*8 + warp;
  int b = t >> 10;
  const float* xr = g_x  + (size_t)t*HH + lane*8;
  const float* tr = g_tb + ((size_t)i*BB + b)*HH + lane*8;
  float4 v0 = *(const float4*)xr;      float4 v1 = *(const float4*)(xr+4);
  float4 t0 = *(const float4*)tr;      float4 t1 = *(const float4*)(tr+4);
  float u[8];
  u[0]=v0.x+t0.x; u[1]=v0.y+t0.y; u[2]=v0.z+t0.z; u[3]=v0.w+t0.w;
  u[4]=v1.x+t1.x; u[5]=v1.y+t1.y; u[6]=v1.z+t1.z; u[7]=v1.w+t1.w;
  float s=0.f, q=0.f;
  #pragma unroll
  for (int j=0;j<8;j++){ s += u[j]; q += u[j]*u[j]; }
  #pragma unroll
  for (int o=16;o>0;o>>=1){
    s += __shfl_xor_sync(0xffffffffu, s, o);
    q += __shfl_xor_sync(0xffffffffu, q, o);
  }
  float mu = s * (1.f/HH);
  float var = q*(1.f/HH) - mu*mu;
  float rs = rsqrtf(var + 1e-5f);
  const float* gp = lg + i*HH + lane*8;
  const float* bp = lb + i*HH + lane*8;
  float4 g0=*(const float4*)gp, g1=*(const float4*)(gp+4);
  float4 e0=*(const float4*)bp, e1=*(const float4*)(bp+4);
  float4 z0, z1;
  z0.x=(u[0]-mu)*rs*g0.x+e0.x; z0.y=(u[1]-mu)*rs*g0.y+e0.y;
  z0.z=(u[2]-mu)*rs*g0.z+e0.z; z0.w=(u[3]-mu)*rs*g0.w+e0.w;
  z1.x=(u[4]-mu)*rs*g1.x+e1.x; z1.y=(u[5]-mu)*rs*g1.y+e1.y;
  z1.z=(u[6]-mu)*rs*g1.z+e1.z; z1.w=(u[7]-mu)*rs*g1.w+e1.w;
  float* zp = G_Z + (size_t)t*HH + lane*8;
  *(float4*)zp = z0; *(float4*)(zp+4) = z1;
}

// ---------------- scan step helpers (4 f32x2 pairs = 8 complex states/thread) ----------------
__device__ __forceinline__ float scan_step_fwd(float zv, u64* sre, u64* sim,
    const u64* wre, const u64* wim, const u64* nwim, const u64* btr, const u64* nbti){
  u64 zz = f2pack(zv, zv);
  u64 acc = 0ULL;
  #pragma unroll
  for (int p=0;p<4;p++){
    u64 t0 = f2fma(nwim[p], sim[p], zz);
    u64 ns = f2fma(wre[p], sim[p], f2mul(wim[p], sre[p]));
    sre[p] = f2fma(wre[p], sre[p], t0);
    sim[p] = ns;
    acc = f2fma(btr[p], sre[p], f2fma(nbti[p], sim[p], acc));
  }
  float2 a = f2unpack(acc);
  return a.x + a.y;
}
__device__ __forceinline__ float scan_step_bwd(float zv, u64* sre, u64* sim,
    const u64* wre, const u64* wim, const u64* nwim, const u64* btr, const u64* nbti){
  u64 acc = 0ULL;
  #pragma unroll
  for (int p=0;p<4;p++)
    acc = f2fma(btr[p], sre[p], f2fma(nbti[p], sim[p], acc));
  u64 zz = f2pack(zv, zv);
  #pragma unroll
  for (int p=0;p<4;p++){
    u64 t0 = f2fma(nwim[p], sim[p], zz);
    u64 ns = f2fma(wre[p], sim[p], f2mul(wim[p], sre[p]));
    sre[p] = f2fma(wre[p], sre[p], t0);
    sim[p] = ns;
  }
  float2 a = f2unpack(acc);
  return a.x + a.y;
}

// ---------------- bidirectional diagonal-SSM scan (R5 config, measured 163us) ----------------
__global__ void __launch_bounds__(128) k_scan(int i){
  int tid = threadIdx.x;
  int bid = blockIdx.x;
  int dir = bid & 1;
  int q   = bid >> 1;
  int htile = q & 15;
  int b = q >> 4;
  int hl = tid >> 3, sg = tid & 7;
  int h = htile*16 + hl;
  bool bit2 = (sg & 4) != 0, bit1 = (sg & 2) != 0, bit0 = (sg & 1) != 0;
  size_t pb = ((size_t)i*HH + h)*NN2 + sg*8;
  const u64* wre_p = (const u64*)(g_wre + pb);
  const u64* wim_p = (const u64*)(g_wim + pb);
  const u64* bre_p = (const u64*)((dir ? g_b1re : g_b0re) + pb);
  const u64* bim_p = (const u64*)((dir ? g_b1im : g_b0im) + pb);
  const u64 SGN = 0x8000000080000000ULL;
  u64 wre[4], wim[4], nwim[4], btr[4], nbti[4];
  #pragma unroll
  for (int p=0;p<4;p++){
    wre[p]=wre_p[p]; wim[p]=wim_p[p]; nwim[p]=wim[p]^SGN;
    btr[p]=bre_p[p]; nbti[p]=bim_p[p]^SGN;
  }
  u64 sre[4]={0,0,0,0}, sim[4]={0,0,0,0};
  int start = dir ? (LLEN-1) : 0;
  const int st = dir ? -HH : HH;
  const float* zc = G_Z + ((size_t)b*LLEN + start)*HH + h;
  float* yc = (dir ? g_yb : g_yf) + ((size_t)b*LLEN + start)*HH + h;

  float zs[8];
  #pragma unroll
  for (int j=0;j<8;j++) zs[j] = zc[j*st];

  #pragma unroll 1
  for (int l0=0;l0<LLEN;l0+=8){
    float zn[8];
    #pragma unroll
    for (int j=0;j<8;j++) zn[j] = zc[(8+j)*st];
    float p[8];
    if (dir == 0){
      #pragma unroll
      for (int j=0;j<8;j++) p[j] = scan_step_fwd(zs[j], sre, sim, wre, wim, nwim, btr, nbti);
    } else {
      #pragma unroll
      for (int j=0;j<8;j++) p[j] = scan_step_bwd(zs[j], sre, sim, wre, wim, nwim, btr, nbti);
    }
    float q1[4];
    #pragma unroll
    for (int j=0;j<4;j++){
      float snd = bit2 ? p[j] : p[j+4];
      float r = __shfl_xor_sync(0xffffffffu, snd, 4);
      q1[j] = (bit2 ? p[j+4] : p[j]) + r;
    }
    float s0 = bit1 ? q1[0] : q1[2];
    float s1v = bit1 ? q1[1] : q1[3];
    float r0 = __shfl_xor_sync(0xffffffffu, s0, 2);
    float r1 = __shfl_xor_sync(0xffffffffu, s1v, 2);
    float u0 = (bit1 ? q1[2] : q1[0]) + r0;
    float u1 = (bit1 ? q1[3] : q1[1]) + r1;
    float s2v = bit0 ? u0 : u1;
    float r2 = __shfl_xor_sync(0xffffffffu, s2v, 1);
    float y  = (bit0 ? u1 : u0) + r2;
    yc[sg*st] = 2.f*y;
    #pragma unroll
    for (int j=0;j<8;j++) zs[j] = zn[j];
    zc += 8*st; yc += 8*st;
  }
}

// ---------------- fp32x2 SIMT GEMM v4: 256 threads, small per-thread tile ----------------
// BM=128, BN=128, BK=32, 256 threads; per-thread 8M x 8N (4 M-pairs in f32x2, acc=32 u64).
// 4 warps/SMSP at 2 blocks/SM (vs 2 in v2) to hide LDS/staging latency.
template<int EPI>
__global__ void __launch_bounds__(256, 2) k_gemm(const float* __restrict__ W,
        const float* __restrict__ bias, const float* __restrict__ feat,
        const float* __restrict__ Wf, const float* __restrict__ bf, int iblk,
        const float* __restrict__ Dp){
  __shared__ float As[32*128];   // [k][m]
  __shared__ float Bs[32*128];   // [k][n]
  __shared__ float Ds[256];
  int tid = threadIdx.x;         // 0..255
  int m0 = blockIdx.x * 128;
  int n0 = blockIdx.y * 128;
  int row = tid & 127;           // A row owned for staging
  int kh  = (tid >> 7) * 16;     // k-half staged by this thread (0 or 16)
  int mi = tid >> 4;             // 0..15 -> rows mi*8..+8
  int ni = tid & 15;             // 0..15 -> cols ni*8..+8
  u64 acc[4][8];
  #pragma unroll
  for (int mp=0;mp<4;mp++)
    #pragma unroll
    for (int n=0;n<8;n++) acc[mp][n] = 0ULL;

  const float* Ap = nullptr;
  const float* Af = nullptr; const float* Ab = nullptr; const float* Az = nullptr;
  if (EPI==0){
    Af = g_yf + (size_t)(m0 + row)*HH;
    Ab = g_yb + (size_t)(m0 + row)*HH;
    Az = G_Z  + (size_t)(m0 + row)*HH;
    Ds[tid] = Dp[tid];
  } else {
    const float* A = (EPI==3) ? g_skip : g_g;
    Ap = A + (size_t)(m0 + row)*HH;
  }

  for (int k0=0;k0<HH;k0+=32){
    __syncthreads();             // prev mainloop done; Ds visible on first iter
    // ---- stage A tile (thread stages its k-half of its row) ----
    #pragma unroll
    for (int c=0;c<4;c++){
      float4 v;
      int kg = kh + c*4;
      if (EPI==0){
        float4 f = *(const float4*)(Af + k0 + kg);
        float4 bb = *(const float4*)(Ab + k0 + kg);
        float4 zz4 = *(const float4*)(Az + k0 + kg);
        float4 d4 = *(const float4*)(Ds + k0 + kg);
        float w0 = f.x + bb.x + zz4.x*d4.x;
        float w1 = f.y + bb.y + zz4.y*d4.y;
        float w2 = f.z + bb.z + zz4.z*d4.z;
        float w3 = f.w + bb.w + zz4.w*d4.w;
        v.x = 0.5f*w0*(1.f + erff(w0*0.70710678118f));
        v.y = 0.5f*w1*(1.f + erff(w1*0.70710678118f));
        v.z = 0.5f*w2*(1.f + erff(w2*0.70710678118f));
        v.w = 0.5f*w3*(1.f + erff(w3*0.70710678118f));
      } else {
        v = *(const float4*)(Ap + k0 + kg);
      }
      As[(kg+0)*128 + row] = v.x;
      As[(kg+1)*128 + row] = v.y;
      As[(kg+2)*128 + row] = v.z;
      As[(kg+3)*128 + row] = v.w;
    }
    // ---- stage B tile (flat conflict-free copy) ----
    #pragma unroll
    for (int it=0;it<4;it++){
      int f = tid + it*256;      // float4 index within 32x128 tile
      int kk = f >> 5;
      int cc = (f & 31) * 4;
      *(float4*)(Bs + kk*128 + cc) = *(const float4*)(W + (size_t)(k0+kk)*HH + n0 + cc);
    }
    __syncthreads();
    // ---- mainloop ----
    #pragma unroll 4
    for (int k=0;k<32;k++){
      const ulonglong2* ap = (const ulonglong2*)(As + k*128 + mi*8);
      ulonglong2 qa0 = ap[0], qa1 = ap[1];
      u64 am[4] = {qa0.x,qa0.y,qa1.x,qa1.y};
      float4 b0 = *(const float4*)(Bs + k*128 + ni*8);
      float4 b1 = *(const float4*)(Bs + k*128 + ni*8 + 4);
      u64 bn[8] = {f2pack(b0.x,b0.x), f2pack(b0.y,b0.y), f2pack(b0.z,b0.z), f2pack(b0.w,b0.w),
                   f2pack(b1.x,b1.x), f2pack(b1.y,b1.y), f2pack(b1.z,b1.z), f2pack(b1.w,b1.w)};
      #pragma unroll
      for (int mp=0;mp<4;mp++)
        #pragma unroll
        for (int n=0;n<8;n++)
          acc[mp][n] = f2fma(am[mp], bn[n], acc[mp][n]);
    }
  }

  int mbase = m0 + mi*8;
  int nbase = n0 + ni*8;
  float bsv[8];
  #pragma unroll
  for (int n=0;n<8;n++) bsv[n] = bias[nbase+n];
  float wf0[8], wf1[8], wf2[8], wf3[8], bfv[8];
  const float* tbp = nullptr;
  if (EPI==0){
    #pragma unroll
    for (int c=0;c<2;c++){
      float4 a0 = *(const float4*)(Wf + 0*HH + nbase + c*4);
      float4 a1 = *(const float4*)(Wf + 1*HH + nbase + c*4);
      float4 a2 = *(const float4*)(Wf + 2*HH + nbase + c*4);
      float4 a3 = *(const float4*)(Wf + 3*HH + nbase + c*4);
      wf0[c*4+0]=a0.x; wf0[c*4+1]=a0.y; wf0[c*4+2]=a0.z; wf0[c*4+3]=a0.w;
      wf1[c*4+0]=a1.x; wf1[c*4+1]=a1.y; wf1[c*4+2]=a1.z; wf1[c*4+3]=a1.w;
      wf2[c*4+0]=a2.x; wf2[c*4+1]=a2.y; wf2[c*4+2]=a2.z; wf2[c*4+3]=a2.w;
      wf3[c*4+0]=a3.x; wf3[c*4+1]=a3.y; wf3[c*4+2]=a3.z; wf3[c*4+3]=a3.w;
    }
    #pragma unroll
    for (int c=0;c<2;c++){
      float4 bv = *(const float4*)(bf + nbase + c*4);
      bfv[c*4+0]=bv.x; bfv[c*4+1]=bv.y; bfv[c*4+2]=bv.z; bfv[c*4+3]=bv.w;
    }
    tbp = g_tb + ((size_t)iblk*BB + (mbase>>10))*HH;   // 8-row group never crosses a batch
  }

  #pragma unroll
  for (int mp=0;mp<4;mp++){
    #pragma unroll
    for (int e=0;e<2;e++){
      size_t t = (size_t)mbase + mp*2 + e;
      float c[8];
      #pragma unroll
      for (int n=0;n<8;n++){
        float2 v = f2unpack(acc[mp][n]);
        c[n] = (e ? v.y : v.x) + bsv[n];
      }
      if (EPI==0){
        float4 fq = *(const float4*)(feat + t*4);
        const float* xp = g_x + t*HH + nbase;
        float4 x0 = *(const float4*)xp, x1 = *(const float4*)(xp+4);
        float xv[8] = {x0.x,x0.y,x0.z,x0.w,x1.x,x1.y,x1.z,x1.w};
        float o[8];
        #pragma unroll
        for (int n=0;n<8;n++){
          float r = c[n] + xv[n] + tbp[nbase+n] + bfv[n]
                  + fq.x*wf0[n] + fq.y*wf1[n] + fq.z*wf2[n] + fq.w*wf3[n];
          o[n] = tanhf(r) * (1.f/(1.f+expf(-r)));
        }
        float* gp = g_g + t*HH + nbase;
        *(float4*)gp     = make_float4(o[0],o[1],o[2],o[3]);
        *(float4*)(gp+4) = make_float4(o[4],o[5],o[6],o[7]);
      } else if (EPI==1){
        float* xp = g_x + t*HH + nbase;
        float4 x0 = *(const float4*)xp, x1 = *(const float4*)(xp+4);
        *(float4*)xp     = make_float4(x0.x+c[0], x0.y+c[1], x0.z+c[2], x0.w+c[3]);
        *(float4*)(xp+4) = make_float4(x1.x+c[4], x1.y+c[5], x1.z+c[6], x1.w+c[7]);
      } else if (EPI==2){
        float* sp = g_skip + t*HH + nbase;
        float4 s0 = *(const float4*)sp, s1 = *(const float4*)(sp+4);
        *(float4*)sp     = make_float4(s0.x+c[0], s0.y+c[1], s0.z+c[2], s0.w+c[3]);
        *(float4*)(sp+4) = make_float4(s1.x+c[4], s1.y+c[5], s1.z+c[6], s1.w+c[7]);
      } else {
        float* hp = g_h + t*HH + nbase;
        *(float4*)hp     = make_float4(fmaxf(c[0],0.f), fmaxf(c[1],0.f), fmaxf(c[2],0.f), fmaxf(c[3],0.f));
        *(float4*)(hp+4) = make_float4(fmaxf(c[4],0.f), fmaxf(c[5],0.f), fmaxf(c[6],0.f), fmaxf(c[7],0.f));
      }
    }
  }
}

// out[t] = h[t,:] . Wh2 + bh2 + input[t]
__global__ void __launch_bounds__(256) k_final(const float* __restrict__ Wh2,
        const float* __restrict__ bh2, const float* __restrict__ input,
        float* __restrict__ out){
  int warp = threadIdx.x >> 5, lane = threadIdx.x & 31;
  int t = blockIdx.x*8 + warp;
  const float* hp = g_h + (size_t)t*HH + lane*8;
  const float* wp = Wh2 + lane*8;
  float4 h0=*(const float4*)hp, h1=*(const float4*)(hp+4);
  float4 w0=*(const float4*)wp, w1=*(const float4*)(wp+4);
  float s = h0.x*w0.x + h0.y*w0.y + h0.z*w0.z + h0.w*w0.w
          + h1.x*w1.x + h1.y*w1.y + h1.z*w1.z + h1.w*w1.w;
  #pragma unroll
  for (int o=16;o>0;o>>=1) s += __shfl_xor_sync(0xffffffffu, s, o);
  if (lane == 0) out[t] = s + bh2[0] + input[t];
}

extern "C" void kernel_launch(void* const* d_in, const int* in_sizes, int n_in,
                              void* d_out, int out_size){
  (void)in_sizes; (void)n_in; (void)out_size;
  const float* input = (const float*)d_in[0];
  const float* tvec  = (const float*)d_in[1];
  const float* feat  = (const float*)d_in[2];
  const float* W_in  = (const float*)d_in[3];
  const float* b_in  = (const float*)d_in[4];
  const float* W_t1  = (const float*)d_in[5];
  const float* b_t1  = (const float*)d_in[6];
  const float* W_t2  = (const float*)d_in[7];
  const float* b_t2  = (const float*)d_in[8];
  const float* Wh1   = (const float*)d_in[9];
  const float* bh1   = (const float*)d_in[10];
  const float* Wh2   = (const float*)d_in[11];
  const float* bh2   = (const float*)d_in[12];
  const float* ln_g  = (const float*)d_in[13];
  const float* ln_b  = (const float*)d_in[14];
  const float* log_dt= (const float*)d_in[15];
  const float* A_re  = (const float*)d_in[16];
  const float* A_im  = (const float*)d_in[17];
  const float* C_re  = (const float*)d_in[18];
  const float* C_im  = (const float*)d_in[19];
  const float* Dd    = (const float*)d_in[20];
  const float* Wo_s4 = (const float*)d_in[21];
  const float* bo_s4 = (const float*)d_in[22];
  const float* Wt    = (const float*)d_in[23];
  const float* bt    = (const float*)d_in[24];
  const float* W1    = (const float*)d_in[25];
  const float* b1    = (const float*)d_in[26];
  const float* W2    = (const float*)d_in[27];
  const float* b2    = (const float*)d_in[28];
  const float* Wf    = (const float*)d_in[29];
  const float* bf    = (const float*)d_in[30];
  float* out = (float*)d_out;

  // launch #1: all setup
  k_setup<<<480 + TT*HH/256, 256>>>(log_dt, A_re, A_im, C_re, C_im,
                                    tvec, W_t1, b_t1, W_t2, b_t2,
                                    Wt, bt, input, W_in, b_in);

  dim3 gg(TT/128, HH/128);   // 256 blocks, single wave at 2 blocks/SM
  for (int i=0;i<NBK;i++){
    k_ln<<<TT/8, 256>>>(i, ln_g, ln_b);        // launch #2 (i=0)
    k_scan<<<512, 128>>>(i);                   // launch #3 (i=0)
    k_gemm<0><<<gg, 256>>>(Wo_s4 + (size_t)i*HH*HH, bo_s4 + i*HH,
                           feat, Wf + (size_t)i*4*HH, bf + i*HH, i,
                           Dd + i*HH);         // launch #4 (i=0) -> profiled slot
    k_gemm<1><<<gg, 256>>>(W1 + (size_t)i*HH*HH, b1 + i*HH, nullptr, nullptr, nullptr, i, nullptr);
    k_gemm<2><<<gg, 256>>>(W2 + (size_t)i*HH*HH, b2 + i*HH, nullptr, nullptr, nullptr, i, nullptr);
  }
  k_gemm<3><<<gg, 256>>>(Wh1, bh1, nullptr, nullptr, nullptr, 0, nullptr);
  k_final<<<TT/8, 256>>>(Wh2, bh2, input, out);
}

// round 17
// speedup vs baseline: 1.6362x; 1.0345x over previous
#include <cuda_runtime.h>
#include <cuda_bf16.h>
#include <cstdint>
#include <math.h>

#define BB   16
#define LLEN 1024
#define HH   256
#define NN2  64
#define NBK  6
#define TT   (BB*LLEN)

typedef unsigned long long u64;

// ---------------- scratch (device globals; no allocation allowed) ----------------
__device__ float g_zbuf[(TT+32)*HH];
#define G_Z (g_zbuf + 16*HH)
__device__ float g_x[TT*HH];
__device__ float g_yf[TT*HH];
__device__ float g_yb[TT*HH];
__device__ float g_g[TT*HH];
__device__ float g_skip[TT*HH];
__device__ float g_h[TT*HH];
__device__ float g_tb[NBK*BB*HH];
__device__ float g_wre[NBK*HH*NN2], g_wim[NBK*HH*NN2];
__device__ float g_b0re[NBK*HH*NN2], g_b0im[NBK*HH*NN2];
__device__ float g_b1re[NBK*HH*NN2], g_b1im[NBK*HH*NN2];

// ---------------- packed fp32x2 helpers (sm_103a) ----------------
__device__ __forceinline__ u64 f2fma(u64 a, u64 b, u64 c){
  u64 d; asm("fma.rn.f32x2 %0, %1, %2, %3;" : "=l"(d) : "l"(a), "l"(b), "l"(c)); return d;
}
__device__ __forceinline__ u64 f2mul(u64 a, u64 b){
  u64 d; asm("mul.rn.f32x2 %0, %1, %2;" : "=l"(d) : "l"(a), "l"(b)); return d;
}
__device__ __forceinline__ u64 f2pack(float lo, float hi){
  u64 d; asm("mov.b64 %0, {%1, %2};" : "=l"(d) : "f"(lo), "f"(hi)); return d;
}
__device__ __forceinline__ float2 f2unpack(u64 v){
  float2 r; asm("mov.b64 {%0, %1}, %2;" : "=f"(r.x), "=f"(r.y) : "l"(v)); return r;
}
__device__ __forceinline__ void cpasync16(uint32_t saddr, const void* gptr){
  asm volatile("cp.async.cg.shared.global [%0], [%1], 16;" :: "r"(saddr), "l"(gptr));
}

// ---------------- launch 1: ALL setup in one kernel ----------------
__global__ void k_setup(const float* __restrict__ log_dt, const float* __restrict__ A_re,
                        const float* __restrict__ A_im, const float* __restrict__ C_re,
                        const float* __restrict__ C_im,
                        const float* __restrict__ tt, const float* __restrict__ W1,
                        const float* __restrict__ b1v, const float* __restrict__ W2,
                        const float* __restrict__ b2v,
                        const float* __restrict__ Wt, const float* __restrict__ bt,
                        const float* __restrict__ input, const float* __restrict__ W_in,
                        const float* __restrict__ b_in){
  __shared__ float s1[128];
  __shared__ float s2[256];
  __shared__ float te[256];
  if (blockIdx.x < 384){
    int idx = blockIdx.x*256 + threadIdx.x;
    int i   = idx / (HH*NN2);
    int rem = idx % (HH*NN2);
    int h   = rem / NN2;
    int n   = rem % NN2;
    float dt  = expf(log_dt[i*HH + h]);
    float are = A_re[idx], aim = A_im[idx];
    float dre = -dt*are, dim = dt*aim;
    float er  = expf(dre);
    float wre = er*cosf(dim), wim = er*sinf(dim);
    g_wre[idx] = wre; g_wim[idx] = wim;
    float dinv = 1.f/(are*are + aim*aim);
    float ure = wre - 1.f, uim = wim;
    float qre = (-ure*are + uim*aim)*dinv;
    float qim = (-uim*are - ure*aim)*dinv;
    size_t c0 = (((size_t)i*2 + 0)*HH + h)*NN2 + n;
    size_t c1 = (((size_t)i*2 + 1)*HH + h)*NN2 + n;
    float cr = C_re[c0], ci = C_im[c0];
    g_b0re[idx] = cr*qre - ci*qim;
    g_b0im[idx] = cr*qim + ci*qre;
    cr = C_re[c1]; ci = C_im[c1];
    g_b1re[idx] = cr*qre - ci*qim;
    g_b1im[idx] = cr*qim + ci*qre;
  } else if (blockIdx.x < 480){
    int blk = blockIdx.x - 384;
    int b = blk & 15;
    int i = blk >> 4;
    int h = threadIdx.x;
    if (h < 128){
      int j = h & 63;
      float fr = expf(-(float)j * (9.210340371976184f/63.f));
      float ang = tt[b]*fr;
      s1[h] = (h < 64) ? sinf(ang) : cosf(ang);
    }
    __syncthreads();
    float acc = b1v[h];
    #pragma unroll 4
    for (int k=0;k<128;k++) acc = fmaf(s1[k], W1[k*HH+h], acc);
    acc = acc / (1.f + expf(-acc));
    s2[h] = acc;
    __syncthreads();
    float a2 = b2v[h];
    #pragma unroll 4
    for (int k=0;k<HH;k++) a2 = fmaf(s2[k], W2[k*HH+h], a2);
    a2 = a2 / (1.f + expf(-a2));
    te[h] = a2;
    __syncthreads();
    float tbv = bt[i*HH + h];
    const float* wp = Wt + (size_t)i*HH*HH + h;
    #pragma unroll 4
    for (int k=0;k<HH;k++) tbv = fmaf(te[k], wp[(size_t)k*HH], tbv);
    g_tb[blk*HH + h] = tbv;
  } else {
    int idx = (blockIdx.x-480)*256 + threadIdx.x;
    int t = idx >> 8; int h = idx & 255;
    g_x[idx] = fmaxf(fmaf(input[t], W_in[h], b_in[h]), 0.f);
    g_skip[idx] = 0.f;
  }
}

// ---------------- u = x + tb; LayerNorm over H -> G_Z ----------------
__global__ void __launch_bounds__(256) k_ln(int i, const float* __restrict__ lg,
                                            const float* __restrict__ lb){
  int warp = threadIdx.x >> 5, lane = threadIdx.x & 31;
  int t = blockIdx.x*8 + warp;
  int b = t >> 10;
  const float* xr = g_x  + (size_t)t*HH + lane*8;
  const float* tr = g_tb + ((size_t)i*BB + b)*HH + lane*8;
  float4 v0 = *(const float4*)xr;      float4 v1 = *(const float4*)(xr+4);
  float4 t0 = *(const float4*)tr;      float4 t1 = *(const float4*)(tr+4);
  float u[8];
  u[0]=v0.x+t0.x; u[1]=v0.y+t0.y; u[2]=v0.z+t0.z; u[3]=v0.w+t0.w;
  u[4]=v1.x+t1.x; u[5]=v1.y+t1.y; u[6]=v1.z+t1.z; u[7]=v1.w+t1.w;
  float s=0.f, q=0.f;
  #pragma unroll
  for (int j=0;j<8;j++){ s += u[j]; q += u[j]*u[j]; }
  #pragma unroll
  for (int o=16;o>0;o>>=1){
    s += __shfl_xor_sync(0xffffffffu, s, o);
    q += __shfl_xor_sync(0xffffffffu, q, o);
  }
  float mu = s * (1.f/HH);
  float var = q*(1.f/HH) - mu*mu;
  float rs = rsqrtf(var + 1e-5f);
  const float* gp = lg + i*HH + lane*8;
  const float* bp = lb + i*HH + lane*8;
  float4 g0=*(const float4*)gp, g1=*(const float4*)(gp+4);
  float4 e0=*(const float4*)bp, e1=*(const float4*)(bp+4);
  float4 z0, z1;
  z0.x=(u[0]-mu)*rs*g0.x+e0.x; z0.y=(u[1]-mu)*rs*g0.y+e0.y;
  z0.z=(u[2]-mu)*rs*g0.z+e0.z; z0.w=(u[3]-mu)*rs*g0.w+e0.w;
  z1.x=(u[4]-mu)*rs*g1.x+e1.x; z1.y=(u[5]-mu)*rs*g1.y+e1.y;
  z1.z=(u[6]-mu)*rs*g1.z+e1.z; z1.w=(u[7]-mu)*rs*g1.w+e1.w;
  float* zp = G_Z + (size_t)t*HH + lane*8;
  *(float4*)zp = z0; *(float4*)(zp+4) = z1;
}

// ---------------- scan step helpers (4 f32x2 pairs = 8 complex states/thread) ----------------
__device__ __forceinline__ float scan_step_fwd(float zv, u64* sre, u64* sim,
    const u64* wre, const u64* wim, const u64* nwim, const u64* btr, const u64* nbti){
  u64 zz = f2pack(zv, zv);
  u64 acc = 0ULL;
  #pragma unroll
  for (int p=0;p<4;p++){
    u64 t0 = f2fma(nwim[p], sim[p], zz);
    u64 ns = f2fma(wre[p], sim[p], f2mul(wim[p], sre[p]));
    sre[p] = f2fma(wre[p], sre[p], t0);
    sim[p] = ns;
    acc = f2fma(btr[p], sre[p], f2fma(nbti[p], sim[p], acc));
  }
  float2 a = f2unpack(acc);
  return a.x + a.y;
}
__device__ __forceinline__ float scan_step_bwd(float zv, u64* sre, u64* sim,
    const u64* wre, const u64* wim, const u64* nwim, const u64* btr, const u64* nbti){
  u64 acc = 0ULL;
  #pragma unroll
  for (int p=0;p<4;p++)
    acc = f2fma(btr[p], sre[p], f2fma(nbti[p], sim[p], acc));
  u64 zz = f2pack(zv, zv);
  #pragma unroll
  for (int p=0;p<4;p++){
    u64 t0 = f2fma(nwim[p], sim[p], zz);
    u64 ns = f2fma(wre[p], sim[p], f2mul(wim[p], sre[p]));
    sre[p] = f2fma(wre[p], sre[p], t0);
    sim[p] = ns;
  }
  float2 a = f2unpack(acc);
  return a.x + a.y;
}

// ---------------- bidirectional diagonal-SSM scan (R5 config, measured 163us) ----------------
__global__ void __launch_bounds__(128) k_scan(int i){
  int tid = threadIdx.x;
  int bid = blockIdx.x;
  int dir = bid & 1;
  int q   = bid >> 1;
  int htile = q & 15;
  int b = q >> 4;
  int hl = tid >> 3, sg = tid & 7;
  int h = htile*16 + hl;
  bool bit2 = (sg & 4) != 0, bit1 = (sg & 2) != 0, bit0 = (sg & 1) != 0;
  size_t pb = ((size_t)i*HH + h)*NN2 + sg*8;
  const u64* wre_p = (const u64*)(g_wre + pb);
  const u64* wim_p = (const u64*)(g_wim + pb);
  const u64* bre_p = (const u64*)((dir ? g_b1re : g_b0re) + pb);
  const u64* bim_p = (const u64*)((dir ? g_b1im : g_b0im) + pb);
  const u64 SGN = 0x8000000080000000ULL;
  u64 wre[4], wim[4], nwim[4], btr[4], nbti[4];
  #pragma unroll
  for (int p=0;p<4;p++){
    wre[p]=wre_p[p]; wim[p]=wim_p[p]; nwim[p]=wim[p]^SGN;
    btr[p]=bre_p[p]; nbti[p]=bim_p[p]^SGN;
  }
  u64 sre[4]={0,0,0,0}, sim[4]={0,0,0,0};
  int start = dir ? (LLEN-1) : 0;
  const int st = dir ? -HH : HH;
  const float* zc = G_Z + ((size_t)b*LLEN + start)*HH + h;
  float* yc = (dir ? g_yb : g_yf) + ((size_t)b*LLEN + start)*HH + h;

  float zs[8];
  #pragma unroll
  for (int j=0;j<8;j++) zs[j] = zc[j*st];

  #pragma unroll 1
  for (int l0=0;l0<LLEN;l0+=8){
    float zn[8];
    #pragma unroll
    for (int j=0;j<8;j++) zn[j] = zc[(8+j)*st];
    float p[8];
    if (dir == 0){
      #pragma unroll
      for (int j=0;j<8;j++) p[j] = scan_step_fwd(zs[j], sre, sim, wre, wim, nwim, btr, nbti);
    } else {
      #pragma unroll
      for (int j=0;j<8;j++) p[j] = scan_step_bwd(zs[j], sre, sim, wre, wim, nwim, btr, nbti);
    }
    float q1[4];
    #pragma unroll
    for (int j=0;j<4;j++){
      float snd = bit2 ? p[j] : p[j+4];
      float r = __shfl_xor_sync(0xffffffffu, snd, 4);
      q1[j] = (bit2 ? p[j+4] : p[j]) + r;
    }
    float s0 = bit1 ? q1[0] : q1[2];
    float s1v = bit1 ? q1[1] : q1[3];
    float r0 = __shfl_xor_sync(0xffffffffu, s0, 2);
    float r1 = __shfl_xor_sync(0xffffffffu, s1v, 2);
    float u0 = (bit1 ? q1[2] : q1[0]) + r0;
    float u1 = (bit1 ? q1[3] : q1[1]) + r1;
    float s2v = bit0 ? u0 : u1;
    float r2 = __shfl_xor_sync(0xffffffffu, s2v, 1);
    float y  = (bit0 ? u1 : u0) + r2;
    yc[sg*st] = 2.f*y;
    #pragma unroll
    for (int j=0;j<8;j++) zs[j] = zn[j];
    zc += 8*st; yc += 8*st;
  }
}

// ---------------- fp32x2 SIMT GEMM v5: v2 tiling + cp.async double-buffered B ----------------
// BM=128, BN=128, BK=32, 128 threads; per-thread 16M x 8N (M-pairs in f32x2, acc=64 u64).
// B tiles stream via cp.async into Bs[2] (flat layout = 16B-chunk compatible);
// wait_group 1 keeps one tile in flight under the mainloop. A staged manually.
template<int EPI>
__global__ void __launch_bounds__(128, 2) k_gemm(const float* __restrict__ W,
        const float* __restrict__ bias, const float* __restrict__ feat,
        const float* __restrict__ Wf, const float* __restrict__ bf, int iblk,
        const float* __restrict__ Dp){
  __shared__ float As[32*128];       // [k][m]
  __shared__ float Bs[2][32*128];    // [buf][k][n]
  int tid = threadIdx.x;
  int m0 = blockIdx.x * 128;
  int n0 = blockIdx.y * 128;
  int mi = tid >> 4;    // 0..7 -> rows mi*16..+16
  int ni = tid & 15;    // 0..15 -> cols ni*8..+8
  u64 acc[8][8];
  #pragma unroll
  for (int mp=0;mp<8;mp++)
    #pragma unroll
    for (int n=0;n<8;n++) acc[mp][n] = 0ULL;

  const float* Ap = nullptr;
  const float* Af = nullptr; const float* Ab = nullptr; const float* Az = nullptr;
  if (EPI==0){
    Af = g_yf + (size_t)(m0 + tid)*HH;
    Ab = g_yb + (size_t)(m0 + tid)*HH;
    Az = G_Z  + (size_t)(m0 + tid)*HH;
  } else {
    const float* A = (EPI==3) ? g_skip : g_g;
    Ap = A + (size_t)(m0 + tid)*HH;
  }

  uint32_t bs_s[2];
  bs_s[0] = (uint32_t)__cvta_generic_to_shared(&Bs[0][0]);
  bs_s[1] = (uint32_t)__cvta_generic_to_shared(&Bs[1][0]);

  // prologue: async-load B tile 0 into buf 0
  #pragma unroll
  for (int it=0;it<8;it++){
    int f = tid + it*128;
    int kk = f >> 5;
    int cc = (f & 31) * 4;
    cpasync16(bs_s[0] + (uint32_t)(kk*128 + cc)*4u, W + (size_t)kk*HH + n0 + cc);
  }
  asm volatile("cp.async.commit_group;" ::: "memory");

  for (int i=0;i<8;i++){
    int k0 = i*32;
    int buf = i & 1;
    __syncthreads();   // previous mainloop done: As and Bs[buf^1] are free
    // ---- stage A tile (manual; gelu-fused for EPI 0) ----
    if (EPI==0){
      #pragma unroll
      for (int c=0;c<8;c++){
        float4 f4 = *(const float4*)(Af + k0 + c*4);
        float4 b4 = *(const float4*)(Ab + k0 + c*4);
        float4 z4 = *(const float4*)(Az + k0 + c*4);
        float4 d4 = *(const float4*)(Dp + k0 + c*4);
        float w0 = f4.x + b4.x + z4.x*d4.x;
        float w1 = f4.y + b4.y + z4.y*d4.y;
        float w2 = f4.z + b4.z + z4.z*d4.z;
        float w3 = f4.w + b4.w + z4.w*d4.w;
        As[(c*4+0)*128 + tid] = 0.5f*w0*(1.f + erff(w0*0.70710678118f));
        As[(c*4+1)*128 + tid] = 0.5f*w1*(1.f + erff(w1*0.70710678118f));
        As[(c*4+2)*128 + tid] = 0.5f*w2*(1.f + erff(w2*0.70710678118f));
        As[(c*4+3)*128 + tid] = 0.5f*w3*(1.f + erff(w3*0.70710678118f));
      }
    } else {
      #pragma unroll
      for (int c=0;c<8;c++){
        float4 v = *(const float4*)(Ap + k0 + c*4);
        As[(c*4+0)*128 + tid] = v.x;
        As[(c*4+1)*128 + tid] = v.y;
        As[(c*4+2)*128 + tid] = v.z;
        As[(c*4+3)*128 + tid] = v.w;
      }
    }
    // ---- issue async B for tile i+1 into buf^1; then pin tile i ----
    if (i < 7){
      #pragma unroll
      for (int it=0;it<8;it++){
        int f = tid + it*128;
        int kk = f >> 5;
        int cc = (f & 31) * 4;
        cpasync16(bs_s[buf^1] + (uint32_t)(kk*128 + cc)*4u,
                  W + (size_t)(k0+32+kk)*HH + n0 + cc);
      }
      asm volatile("cp.async.commit_group;" ::: "memory");
      asm volatile("cp.async.wait_group 1;" ::: "memory");
    } else {
      asm volatile("cp.async.wait_group 0;" ::: "memory");
    }
    __syncthreads();
    // ---- mainloop on Bs[buf] ----
    const float* Bsc = &Bs[buf][0];
    #pragma unroll 4
    for (int k=0;k<32;k++){
      const ulonglong2* ap = (const ulonglong2*)(As + k*128 + mi*16);
      ulonglong2 qa0 = ap[0], qa1 = ap[1], qa2 = ap[2], qa3 = ap[3];
      u64 am[8] = {qa0.x,qa0.y,qa1.x,qa1.y,qa2.x,qa2.y,qa3.x,qa3.y};
      float4 b0 = *(const float4*)(Bsc + k*128 + ni*8);
      float4 b1 = *(const float4*)(Bsc + k*128 + ni*8 + 4);
      u64 bn[8] = {f2pack(b0.x,b0.x), f2pack(b0.y,b0.y), f2pack(b0.z,b0.z), f2pack(b0.w,b0.w),
                   f2pack(b1.x,b1.x), f2pack(b1.y,b1.y), f2pack(b1.z,b1.z), f2pack(b1.w,b1.w)};
      #pragma unroll
      for (int mp=0;mp<8;mp++)
        #pragma unroll
        for (int n=0;n<8;n++)
          acc[mp][n] = f2fma(am[mp], bn[n], acc[mp][n]);
    }
  }

  int mbase = m0 + mi*16;
  int nbase = n0 + ni*8;
  float bsv[8];
  #pragma unroll
  for (int n=0;n<8;n++) bsv[n] = bias[nbase+n];
  float wf0[8], wf1[8], wf2[8], wf3[8], bfv[8];
  const float* tbp = nullptr;
  if (EPI==0){
    #pragma unroll
    for (int c=0;c<2;c++){
      float4 a0 = *(const float4*)(Wf + 0*HH + nbase + c*4);
      float4 a1 = *(const float4*)(Wf + 1*HH + nbase + c*4);
      float4 a2 = *(const float4*)(Wf + 2*HH + nbase + c*4);
      float4 a3 = *(const float4*)(Wf + 3*HH + nbase + c*4);
      wf0[c*4+0]=a0.x; wf0[c*4+1]=a0.y; wf0[c*4+2]=a0.z; wf0[c*4+3]=a0.w;
      wf1[c*4+0]=a1.x; wf1[c*4+1]=a1.y; wf1[c*4+2]=a1.z; wf1[c*4+3]=a1.w;
      wf2[c*4+0]=a2.x; wf2[c*4+1]=a2.y; wf2[c*4+2]=a2.z; wf2[c*4+3]=a2.w;
      wf3[c*4+0]=a3.x; wf3[c*4+1]=a3.y; wf3[c*4+2]=a3.z; wf3[c*4+3]=a3.w;
    }
    #pragma unroll
    for (int c=0;c<2;c++){
      float4 bv = *(const float4*)(bf + nbase + c*4);
      bfv[c*4+0]=bv.x; bfv[c*4+1]=bv.y; bfv[c*4+2]=bv.z; bfv[c*4+3]=bv.w;
    }
    tbp = g_tb + ((size_t)iblk*BB + (mbase>>10))*HH;   // 16-row group never crosses a batch
  }

  #pragma unroll
  for (int mp=0;mp<8;mp++){
    #pragma unroll
    for (int e=0;e<2;e++){
      size_t t = (size_t)mbase + mp*2 + e;
      float c[8];
      #pragma unroll
      for (int n=0;n<8;n++){
        float2 v = f2unpack(acc[mp][n]);
        c[n] = (e ? v.y : v.x) + bsv[n];
      }
      if (EPI==0){
        float4 fq = *(const float4*)(feat + t*4);
        const float* xp = g_x + t*HH + nbase;
        float4 x0 = *(const float4*)xp, x1 = *(const float4*)(xp+4);
        float xv[8] = {x0.x,x0.y,x0.z,x0.w,x1.x,x1.y,x1.z,x1.w};
        float o[8];
        #pragma unroll
        for (int n=0;n<8;n++){
          float r = c[n] + xv[n] + tbp[nbase+n] + bfv[n]
                  + fq.x*wf0[n] + fq.y*wf1[n] + fq.z*wf2[n] + fq.w*wf3[n];
          o[n] = tanhf(r) * (1.f/(1.f+expf(-r)));
        }
        float* gp = g_g + t*HH + nbase;
        *(float4*)gp     = make_float4(o[0],o[1],o[2],o[3]);
        *(float4*)(gp+4) = make_float4(o[4],o[5],o[6],o[7]);
      } else if (EPI==1){
        float* xp = g_x + t*HH + nbase;
        float4 x0 = *(const float4*)xp, x1 = *(const float4*)(xp+4);
        *(float4*)xp     = make_float4(x0.x+c[0], x0.y+c[1], x0.z+c[2], x0.w+c[3]);
        *(float4*)(xp+4) = make_float4(x1.x+c[4], x1.y+c[5], x1.z+c[6], x1.w+c[7]);
      } else if (EPI==2){
        float* sp = g_skip + t*HH + nbase;
        float4 s0 = *(const float4*)sp, s1 = *(const float4*)(sp+4);
        *(float4*)sp     = make_float4(s0.x+c[0], s0.y+c[1], s0.z+c[2], s0.w+c[3]);
        *(float4*)(sp+4) = make_float4(s1.x+c[4], s1.y+c[5], s1.z+c[6], s1.w+c[7]);
      } else {
        float* hp = g_h + t*HH + nbase;
        *(float4*)hp     = make_float4(fmaxf(c[0],0.f), fmaxf(c[1],0.f), fmaxf(c[2],0.f), fmaxf(c[3],0.f));
        *(float4*)(hp+4) = make_float4(fmaxf(c[4],0.f), fmaxf(c[5],0.f), fmaxf(c[6],0.f), fmaxf(c[7],0.f));
      }
    }
  }
}

// out[t] = h[t,:] . Wh2 + bh2 + input[t]
__global__ void __launch_bounds__(256) k_final(const float* __restrict__ Wh2,
        const float* __restrict__ bh2, const float* __restrict__ input,
        float* __restrict__ out){
  int warp = threadIdx.x >> 5, lane = threadIdx.x & 31;
  int t = blockIdx.x*8 + warp;
  const float* hp = g_h + (size_t)t*HH + lane*8;
  const float* wp = Wh2 + lane*8;
  float4 h0=*(const float4*)hp, h1=*(const float4*)(hp+4);
  float4 w0=*(const float4*)wp, w1=*(const float4*)(wp+4);
  float s = h0.x*w0.x + h0.y*w0.y + h0.z*w0.z + h0.w*w0.w
          + h1.x*w1.x + h1.y*w1.y + h1.z*w1.z + h1.w*w1.w;
  #pragma unroll
  for (int o=16;o>0;o>>=1) s += __shfl_xor_sync(0xffffffffu, s, o);
  if (lane == 0) out[t] = s + bh2[0] + input[t];
}

extern "C" void kernel_launch(void* const* d_in, const int* in_sizes, int n_in,
                              void* d_out, int out_size){
  (void)in_sizes; (void)n_in; (void)out_size;
  const float* input = (const float*)d_in[0];
  const float* tvec  = (const float*)d_in[1];
  const float* feat  = (const float*)d_in[2];
  const float* W_in  = (const float*)d_in[3];
  const float* b_in  = (const float*)d_in[4];
  const float* W_t1  = (const float*)d_in[5];
  const float* b_t1  = (const float*)d_in[6];
  const float* W_t2  = (const float*)d_in[7];
  const float* b_t2  = (const float*)d_in[8];
  const float* Wh1   = (const float*)d_in[9];
  const float* bh1   = (const float*)d_in[10];
  const float* Wh2   = (const float*)d_in[11];
  const float* bh2   = (const float*)d_in[12];
  const float* ln_g  = (const float*)d_in[13];
  const float* ln_b  = (const float*)d_in[14];
  const float* log_dt= (const float*)d_in[15];
  const float* A_re  = (const float*)d_in[16];
  const float* A_im  = (const float*)d_in[17];
  const float* C_re  = (const float*)d_in[18];
  const float* C_im  = (const float*)d_in[19];
  const float* Dd    = (const float*)d_in[20];
  const float* Wo_s4 = (const float*)d_in[21];
  const float* bo_s4 = (const float*)d_in[22];
  const float* Wt    = (const float*)d_in[23];
  const float* bt    = (const float*)d_in[24];
  const float* W1    = (const float*)d_in[25];
  const float* b1    = (const float*)d_in[26];
  const float* W2    = (const float*)d_in[27];
  const float* b2    = (const float*)d_in[28];
  const float* Wf    = (const float*)d_in[29];
  const float* bf    = (const float*)d_in[30];
  float* out = (float*)d_out;

  // launch #1: all setup
  k_setup<<<480 + TT*HH/256, 256>>>(log_dt, A_re, A_im, C_re, C_im,
                                    tvec, W_t1, b_t1, W_t2, b_t2,
                                    Wt, bt, input, W_in, b_in);

  dim3 gg(TT/128, HH/128);   // 256 blocks, single wave at 2 blocks/SM
  for (int i=0;i<NBK;i++){
    k_ln<<<TT/8, 256>>>(i, ln_g, ln_b);        // launch #2 (i=0)
    k_scan<<<512, 128>>>(i);                   // launch #3 (i=0)
    k_gemm<0><<<gg, 128>>>(Wo_s4 + (size_t)i*HH*HH, bo_s4 + i*HH,
                           feat, Wf + (size_t)i*4*HH, bf + i*HH, i,
                           Dd + i*HH);         // launch #4 (i=0) -> profiled slot
    k_gemm<1><<<gg, 128>>>(W1 + (size_t)i*HH*HH, b1 + i*HH, nullptr, nullptr, nullptr, i, nullptr);
    k_gemm<2><<<gg, 128>>>(W2 + (size_t)i*HH*HH, b2 + i*HH, nullptr, nullptr, nullptr, i, nullptr);
  }
  k_gemm<3><<<gg, 128>>>(Wh1, bh1, nullptr, nullptr, nullptr, 0, nullptr);
  k_final<<<TT/8, 256>>>(Wh2, bh2, input, out);
}